// round 6
// baseline (speedup 1.0000x reference)
#include <cuda_runtime.h>

#define N_NODES 100000
#define N_EDGES 1600000
#define IN_F    128
#define HID     64
#define N_CLS   4
#define BN_EPS  1e-5f

#define SCAN_BS   512
#define SCAN_NB   ((N_NODES + SCAN_BS - 1) / SCAN_BS)   // 196
#define NGROUPS   (N_NODES / 16)                        // 6250 exactly
#define GATHER_GRID 2000

// ------------------------- device scratch (no allocs allowed) ---------------
__device__ __align__(256) int   g_cnt[N_NODES];
__device__ __align__(256) int   g_off[N_NODES + 1];
__device__ __align__(256) int   g_cur[N_NODES];
__device__ __align__(256) int   g_bsum[SCAN_NB];
__device__ __align__(256) int2  g_edge[N_EDGES];            // {src, coef bits}
__device__ __align__(256) float g_dinv[N_NODES];
__device__ __align__(256) float g_bufA[N_NODES * HID];      // 25.6 MB
__device__ __align__(256) float g_bufB[N_NODES * HID];      // 25.6 MB
__device__ __align__(256) float g_stats1[2 * HID];
__device__ __align__(256) float g_stats2[2 * HID];

// ------------------------- graph prep ----------------------------------------
__global__ void k_zero_cnt() {
    int i = blockIdx.x * blockDim.x + threadIdx.x;
    if (i < N_NODES) g_cnt[i] = 0;
    if (i < 2 * HID) { g_stats1[i] = 0.0f; g_stats2[i] = 0.0f; }
}

// edge_index is int32 (JAX default: int64 request silently becomes int32).
__global__ void k_count(const int* __restrict__ ei) {
    int e = blockIdx.x * blockDim.x + threadIdx.x;
    if (e >= N_EDGES) return;
    int d = ei[N_EDGES + e];
    if ((unsigned)d >= N_NODES) d = 0;
    atomicAdd(&g_cnt[d], 1);
}

// exclusive scan of g_cnt -> g_off, 3 stages; stage 1 also computes dinv
__global__ void k_scan1() {
    __shared__ int sh[SCAN_BS];
    int t = threadIdx.x;
    int i = blockIdx.x * SCAN_BS + t;
    int v = (i < N_NODES) ? g_cnt[i] : 0;
    if (i < N_NODES) g_dinv[i] = rsqrtf((float)(v + 1));   // +1 self-loop
    sh[t] = v;
    __syncthreads();
    for (int o = 1; o < SCAN_BS; o <<= 1) {
        int x = (t >= o) ? sh[t - o] : 0;
        __syncthreads();
        sh[t] += x;
        __syncthreads();
    }
    if (i < N_NODES) g_off[i] = sh[t] - v;          // exclusive within block
    if (t == SCAN_BS - 1) g_bsum[blockIdx.x] = sh[t];
}

__global__ void k_scan2() {
    __shared__ int sh[256];
    int t = threadIdx.x;
    int v = (t < SCAN_NB) ? g_bsum[t] : 0;
    sh[t] = v;
    __syncthreads();
    for (int o = 1; o < 256; o <<= 1) {
        int x = (t >= o) ? sh[t - o] : 0;
        __syncthreads();
        sh[t] += x;
        __syncthreads();
    }
    if (t < SCAN_NB) g_bsum[t] = sh[t] - v;         // exclusive
}

__global__ void k_scan3() {
    int i = blockIdx.x * blockDim.x + threadIdx.x;
    if (i == 0) g_off[N_NODES] = N_EDGES;
    if (i >= N_NODES) return;
    int o = g_off[i] + g_bsum[i / SCAN_BS];
    g_off[i] = o;
    g_cur[i] = o;
}

__global__ void k_fill(const int* __restrict__ ei) {
    int e = blockIdx.x * blockDim.x + threadIdx.x;
    if (e >= N_EDGES) return;
    int s = ei[e];
    int d = ei[N_EDGES + e];
    if ((unsigned)s >= N_NODES) s = 0;
    if ((unsigned)d >= N_NODES) d = 0;
    int slot = atomicAdd(&g_cur[d], 1);
    if ((unsigned)slot >= N_EDGES) return;          // defensive
    float cf = g_dinv[s] * g_dinv[d];
    g_edge[slot] = make_int2(s, __float_as_int(cf));
}

// ------------------------- GEMM: [N, K] x [K, 64] -----------------------------
// Block: 256 threads, 32 rows per block. 100000 = 3125 * 32 exactly.
// AFF: apply per-column BN affine + ReLU to X while staging (column k of X).
template <int K, bool AFF>
__global__ void k_gemm_n64(const float* __restrict__ X, const float* __restrict__ W,
                           float* __restrict__ T, const float* __restrict__ stats,
                           const float* __restrict__ gam, const float* __restrict__ bet) {
    __shared__ float sW[K * 64];
    __shared__ float sX[32 * K];
    __shared__ float sa[AFF ? K : 1];
    __shared__ float sd[AFF ? K : 1];
    const int tid = threadIdx.x;

    for (int i = tid * 4; i < K * 64; i += 256 * 4)
        *(float4*)&sW[i] = *(const float4*)&W[i];

    if (AFF && tid < K) {
        const float invN = 1.0f / (float)N_NODES;
        float m  = stats[tid] * invN;
        float vv = stats[HID + tid] * invN - m * m;
        float rs = rsqrtf(vv + BN_EPS);
        float a  = rs * gam[tid];
        sa[tid] = a;
        sd[tid] = bet[tid] - m * a;
    }
    if (AFF) __syncthreads();

    const int row0 = blockIdx.x * 32;
    for (int i = tid * 4; i < 32 * K; i += 256 * 4) {
        int r = i / K, k = i % K;
        float4 v = *(const float4*)&X[(row0 + r) * K + k];
        if (AFF) {
            v.x = fmaxf(v.x * sa[k]     + sd[k],     0.0f);
            v.y = fmaxf(v.y * sa[k + 1] + sd[k + 1], 0.0f);
            v.z = fmaxf(v.z * sa[k + 2] + sd[k + 2], 0.0f);
            v.w = fmaxf(v.w * sa[k + 3] + sd[k + 3], 0.0f);
        }
        *(float4*)&sX[i] = v;
    }
    __syncthreads();

    const int r  = tid >> 3;        // 0..31
    const int c0 = (tid & 7) * 8;   // 0..56
    float acc[8];
#pragma unroll
    for (int c = 0; c < 8; c++) acc[c] = 0.0f;

    const float* xr = &sX[r * K];
    for (int k = 0; k < K; k += 4) {
        float4 xv = *(const float4*)&xr[k];
        float xs[4] = {xv.x, xv.y, xv.z, xv.w};
#pragma unroll
        for (int kk = 0; kk < 4; kk++) {
            float4 w0 = *(const float4*)&sW[(k + kk) * 64 + c0];
            float4 w1 = *(const float4*)&sW[(k + kk) * 64 + c0 + 4];
            acc[0] += xs[kk] * w0.x; acc[1] += xs[kk] * w0.y;
            acc[2] += xs[kk] * w0.z; acc[3] += xs[kk] * w0.w;
            acc[4] += xs[kk] * w1.x; acc[5] += xs[kk] * w1.y;
            acc[6] += xs[kk] * w1.z; acc[7] += xs[kk] * w1.w;
        }
    }
    float* o = &T[(row0 + r) * 64 + c0];
    *(float4*)o       = make_float4(acc[0], acc[1], acc[2], acc[3]);
    *(float4*)(o + 4) = make_float4(acc[4], acc[5], acc[6], acc[7]);
}

// ------------------------- GEMM: [N, 64] x [64, 4], BN2 affine fused ----------
__global__ void k_gemm_n4(const float* __restrict__ H, const float* __restrict__ W,
                          float* __restrict__ T, const float* __restrict__ stats,
                          const float* __restrict__ gam, const float* __restrict__ bet) {
    __shared__ float sH[64 * 65];
    __shared__ float sW[64 * 4];
    __shared__ float sa[64], sd[64];
    const int tid = threadIdx.x;
    sW[tid] = W[tid];   // 256 elems exactly
    if (tid < 64) {
        const float invN = 1.0f / (float)N_NODES;
        float m  = stats[tid] * invN;
        float vv = stats[HID + tid] * invN - m * m;
        float rs = rsqrtf(vv + BN_EPS);
        float a  = rs * gam[tid];
        sa[tid] = a;
        sd[tid] = bet[tid] - m * a;
    }
    __syncthreads();
    const int row0 = blockIdx.x * 64;
    for (int i = tid; i < 64 * 64; i += 256) {
        int r = i >> 6, k = i & 63;
        float v = 0.0f;
        if (row0 + r < N_NODES) {
            v = H[(row0 + r) * 64 + k];
            v = fmaxf(v * sa[k] + sd[k], 0.0f);
        }
        sH[r * 65 + k] = v;
    }
    __syncthreads();
    const int r = tid >> 2, c = tid & 3;
    float acc = 0.0f;
#pragma unroll 8
    for (int k = 0; k < 64; k++)
        acc += sH[r * 65 + k] * sW[k * 4 + c];
    if (row0 + r < N_NODES) T[(row0 + r) * 4 + c] = acc;
}

// ------------------------- aggregation (gather, HID=64) + fused BN stats ------
// 16 threads per node, each owning 4 contiguous columns; grid-strided groups.
// Edge loop unrolled x4 with batched loads for MLP.
__global__ void k_gather64(const float* __restrict__ T, const float* __restrict__ b,
                           float* __restrict__ A, float* __restrict__ stats) {
    const int tid = threadIdx.x;
    const int sub = tid >> 4;       // node-in-group 0..15
    const int c   = (tid & 15) * 4; // column group
    const float4 bb = *(const float4*)&b[c];

    float s0 = 0, s1 = 0, s2 = 0, s3 = 0;
    float q0 = 0, q1 = 0, q2 = 0, q3 = 0;

    for (int grp = blockIdx.x; grp < NGROUPS; grp += gridDim.x) {
        const int node = grp * 16 + sub;
        const int beg = g_off[node];
        const int end = g_off[node + 1];
        const float dv = g_dinv[node];
        const float sc = dv * dv;
        float4 t = *(const float4*)&T[node * 64 + c];
        float4 acc;
        acc.x = t.x * sc + bb.x; acc.y = t.y * sc + bb.y;
        acc.z = t.z * sc + bb.z; acc.w = t.w * sc + bb.w;

        int j = beg;
        for (; j + 4 <= end; j += 4) {
            // batch edge records, then issue 4 independent row loads
            int2 e0 = g_edge[j];
            int2 e1 = g_edge[j + 1];
            int2 e2 = g_edge[j + 2];
            int2 e3 = g_edge[j + 3];
            float4 v0 = *(const float4*)&T[e0.x * 64 + c];
            float4 v1 = *(const float4*)&T[e1.x * 64 + c];
            float4 v2 = *(const float4*)&T[e2.x * 64 + c];
            float4 v3 = *(const float4*)&T[e3.x * 64 + c];
            float c0f = __int_as_float(e0.y), c1f = __int_as_float(e1.y);
            float c2f = __int_as_float(e2.y), c3f = __int_as_float(e3.y);
            acc.x += v0.x * c0f; acc.y += v0.y * c0f; acc.z += v0.z * c0f; acc.w += v0.w * c0f;
            acc.x += v1.x * c1f; acc.y += v1.y * c1f; acc.z += v1.z * c1f; acc.w += v1.w * c1f;
            acc.x += v2.x * c2f; acc.y += v2.y * c2f; acc.z += v2.z * c2f; acc.w += v2.w * c2f;
            acc.x += v3.x * c3f; acc.y += v3.y * c3f; acc.z += v3.z * c3f; acc.w += v3.w * c3f;
        }
        for (; j < end; j++) {
            int2  e  = g_edge[j];
            float cf = __int_as_float(e.y);
            float4 v = *(const float4*)&T[e.x * 64 + c];
            acc.x += v.x * cf; acc.y += v.y * cf;
            acc.z += v.z * cf; acc.w += v.w * cf;
        }
        *(float4*)&A[node * 64 + c] = acc;

        s0 += acc.x; q0 += acc.x * acc.x;
        s1 += acc.y; q1 += acc.y * acc.y;
        s2 += acc.z; q2 += acc.z * acc.z;
        s3 += acc.w; q3 += acc.w * acc.w;
    }

    __shared__ float ssum[64], ssq[64];
    if (tid < 64) { ssum[tid] = 0.0f; ssq[tid] = 0.0f; }
    __syncthreads();
    atomicAdd(&ssum[c],     s0); atomicAdd(&ssq[c],     q0);
    atomicAdd(&ssum[c + 1], s1); atomicAdd(&ssq[c + 1], q1);
    atomicAdd(&ssum[c + 2], s2); atomicAdd(&ssq[c + 2], q2);
    atomicAdd(&ssum[c + 3], s3); atomicAdd(&ssq[c + 3], q3);
    __syncthreads();
    if (tid < 64) {
        atomicAdd(&stats[tid],       ssum[tid]);
        atomicAdd(&stats[HID + tid], ssq[tid]);
    }
}

// ------------------------- aggregation (gather, N_CLS=4) ----------------------
__global__ void k_gather4(const float* __restrict__ T, const float* __restrict__ b,
                          float* __restrict__ O) {
    int node = blockIdx.x * blockDim.x + threadIdx.x;
    if (node >= N_NODES) return;
    float dv = g_dinv[node];
    float sc = dv * dv;
    float4 t = *(const float4*)&T[node * 4];
    float4 acc;
    acc.x = t.x * sc + b[0]; acc.y = t.y * sc + b[1];
    acc.z = t.z * sc + b[2]; acc.w = t.w * sc + b[3];
    int beg = g_off[node], end = g_off[node + 1];
    int j = beg;
    for (; j + 4 <= end; j += 4) {
        int2 e0 = g_edge[j];
        int2 e1 = g_edge[j + 1];
        int2 e2 = g_edge[j + 2];
        int2 e3 = g_edge[j + 3];
        float4 v0 = *(const float4*)&T[e0.x * 4];
        float4 v1 = *(const float4*)&T[e1.x * 4];
        float4 v2 = *(const float4*)&T[e2.x * 4];
        float4 v3 = *(const float4*)&T[e3.x * 4];
        float c0f = __int_as_float(e0.y), c1f = __int_as_float(e1.y);
        float c2f = __int_as_float(e2.y), c3f = __int_as_float(e3.y);
        acc.x += v0.x * c0f; acc.y += v0.y * c0f; acc.z += v0.z * c0f; acc.w += v0.w * c0f;
        acc.x += v1.x * c1f; acc.y += v1.y * c1f; acc.z += v1.z * c1f; acc.w += v1.w * c1f;
        acc.x += v2.x * c2f; acc.y += v2.y * c2f; acc.z += v2.z * c2f; acc.w += v2.w * c2f;
        acc.x += v3.x * c3f; acc.y += v3.y * c3f; acc.z += v3.z * c3f; acc.w += v3.w * c3f;
    }
    for (; j < end; j++) {
        int2  e  = g_edge[j];
        float cf = __int_as_float(e.y);
        float4 v = *(const float4*)&T[e.x * 4];
        acc.x += v.x * cf; acc.y += v.y * cf;
        acc.z += v.z * cf; acc.w += v.w * cf;
    }
    *(float4*)&O[node * 4] = acc;
}

// ------------------------- launch --------------------------------------------
extern "C" void kernel_launch(void* const* d_in, const int* in_sizes, int n_in,
                              void* d_out, int out_size) {
    const float* x   = (const float*)d_in[0];
    const int*   ei  = (const int*)d_in[1];      // int32 (JAX default int)
    const float* W1  = (const float*)d_in[2];
    const float* b1  = (const float*)d_in[3];
    const float* g1  = (const float*)d_in[4];
    const float* be1 = (const float*)d_in[5];
    const float* W2  = (const float*)d_in[6];
    const float* b2  = (const float*)d_in[7];
    const float* g2  = (const float*)d_in[8];
    const float* be2 = (const float*)d_in[9];
    const float* W3  = (const float*)d_in[10];
    const float* b3  = (const float*)d_in[11];
    float* out = (float*)d_out;

    float *bufA, *bufB, *st1, *st2;
    cudaGetSymbolAddress((void**)&bufA, g_bufA);
    cudaGetSymbolAddress((void**)&bufB, g_bufB);
    cudaGetSymbolAddress((void**)&st1,  g_stats1);
    cudaGetSymbolAddress((void**)&st2,  g_stats2);

    const int TB = 256;
    const int gN   = (N_NODES + TB - 1) / TB;          // 391
    const int gE   = (N_EDGES + TB - 1) / TB;          // 6250
    const int gM32 = N_NODES / 32;                     // 3125
    const int gM64 = (N_NODES + 63) / 64;              // 1563

    // graph prep: degrees (+stat zero), scan (+dinv), CSR build
    k_zero_cnt<<<gN, TB>>>();
    k_count<<<gE, TB>>>(ei);
    k_scan1<<<SCAN_NB, SCAN_BS>>>();
    k_scan2<<<1, 256>>>();
    k_scan3<<<gN, TB>>>();
    k_fill<<<gE, TB>>>(ei);

    // layer 1: t1 = x @ W1 ; h1 = aggregate(t1) (+BN1 stats)
    k_gemm_n64<IN_F, false><<<gM32, TB>>>(x, W1, bufA, nullptr, nullptr, nullptr);
    k_gather64<<<GATHER_GRID, TB>>>(bufA, b1, bufB, st1);

    // layer 2: t2 = relu(bn1(h1)) @ W2 ; h2 = aggregate(t2) (+BN2 stats)
    k_gemm_n64<HID, true><<<gM32, TB>>>(bufB, W2, bufA, st1, g1, be1);
    k_gather64<<<GATHER_GRID, TB>>>(bufA, b2, bufB, st2);

    // layer 3: t3 = relu(bn2(h2)) @ W3 ; out = aggregate(t3)
    k_gemm_n4<<<gM64, TB>>>(bufB, W3, bufA, st2, g2, be2);
    k_gather4<<<gN, TB>>>(bufA, b3, out);
}

// round 7
// speedup vs baseline: 1.7081x; 1.7081x over previous
#include <cuda_runtime.h>

#define N_NODES 100000
#define N_EDGES 1600000
#define IN_F    128
#define HID     64
#define N_CLS   4
#define BN_EPS  1e-5f

#define SCAN_BS   512
#define SCAN_NB   ((N_NODES + SCAN_BS - 1) / SCAN_BS)   // 196
#define NGROUPS   (N_NODES / 16)                        // 6250 exactly
#define GATHER_GRID 2000

// ------------------------- device scratch (no allocs allowed) ---------------
__device__ __align__(256) int   g_cnt[N_NODES];
__device__ __align__(256) int   g_off[N_NODES + 1];
__device__ __align__(256) int   g_cur[N_NODES];
__device__ __align__(256) int   g_bsum[SCAN_NB];
__device__ __align__(256) int2  g_edge[N_EDGES];            // {src, coef bits}
__device__ __align__(256) float g_dinv[N_NODES];
__device__ __align__(256) float g_bufA[N_NODES * HID];      // 25.6 MB
__device__ __align__(256) float g_bufB[N_NODES * HID];      // 25.6 MB
__device__ __align__(256) float g_stats1[2 * HID];
__device__ __align__(256) float g_stats2[2 * HID];

// ------------------------- graph prep ----------------------------------------
__global__ void k_zero_cnt() {
    int i = blockIdx.x * blockDim.x + threadIdx.x;
    if (i < N_NODES) g_cnt[i] = 0;
    if (i < 2 * HID) { g_stats1[i] = 0.0f; g_stats2[i] = 0.0f; }
}

// edge_index is int32 (JAX default: int64 request silently becomes int32).
__global__ void k_count(const int* __restrict__ ei) {
    int e = blockIdx.x * blockDim.x + threadIdx.x;
    if (e >= N_EDGES) return;
    int d = ei[N_EDGES + e];
    if ((unsigned)d >= N_NODES) d = 0;
    atomicAdd(&g_cnt[d], 1);
}

// exclusive scan of g_cnt -> g_off, 3 stages; stage 1 also computes dinv
__global__ void k_scan1() {
    __shared__ int sh[SCAN_BS];
    int t = threadIdx.x;
    int i = blockIdx.x * SCAN_BS + t;
    int v = (i < N_NODES) ? g_cnt[i] : 0;
    if (i < N_NODES) g_dinv[i] = rsqrtf((float)(v + 1));   // +1 self-loop
    sh[t] = v;
    __syncthreads();
    for (int o = 1; o < SCAN_BS; o <<= 1) {
        int x = (t >= o) ? sh[t - o] : 0;
        __syncthreads();
        sh[t] += x;
        __syncthreads();
    }
    if (i < N_NODES) g_off[i] = sh[t] - v;          // exclusive within block
    if (t == SCAN_BS - 1) g_bsum[blockIdx.x] = sh[t];
}

__global__ void k_scan2() {
    __shared__ int sh[256];
    int t = threadIdx.x;
    int v = (t < SCAN_NB) ? g_bsum[t] : 0;
    sh[t] = v;
    __syncthreads();
    for (int o = 1; o < 256; o <<= 1) {
        int x = (t >= o) ? sh[t - o] : 0;
        __syncthreads();
        sh[t] += x;
        __syncthreads();
    }
    if (t < SCAN_NB) g_bsum[t] = sh[t] - v;         // exclusive
}

__global__ void k_scan3() {
    int i = blockIdx.x * blockDim.x + threadIdx.x;
    if (i == 0) g_off[N_NODES] = N_EDGES;
    if (i >= N_NODES) return;
    int o = g_off[i] + g_bsum[i / SCAN_BS];
    g_off[i] = o;
    g_cur[i] = o;
}

__global__ void k_fill(const int* __restrict__ ei) {
    int e = blockIdx.x * blockDim.x + threadIdx.x;
    if (e >= N_EDGES) return;
    int s = ei[e];
    int d = ei[N_EDGES + e];
    if ((unsigned)s >= N_NODES) s = 0;
    if ((unsigned)d >= N_NODES) d = 0;
    int slot = atomicAdd(&g_cur[d], 1);
    if ((unsigned)slot >= N_EDGES) return;          // defensive
    float cf = g_dinv[s] * g_dinv[d];
    g_edge[slot] = make_int2(s, __float_as_int(cf));
}

// ------------------------- GEMM: [N, K] x [K, 64] -----------------------------
// Block tile M=128, N=64; 256 threads; thread tile 4 rows x 8 cols; K chunk 32.
// X staged transposed: sXT[k][r] so each thread reads its 4 row-values with one
// LDS.128 per k. 3 LDS.128 per 32 FFMA per thread (1.5 B/FFMA).
// AFF: apply per-column BN affine + ReLU to X while staging.
template <int K, bool AFF>
__global__ __launch_bounds__(256) void k_gemm_n64(
        const float* __restrict__ X, const float* __restrict__ W,
        float* __restrict__ T, const float* __restrict__ stats,
        const float* __restrict__ gam, const float* __restrict__ bet) {
    constexpr int KC = 32;
    __shared__ float sXT[KC][132];          // [k][row], pitch 132 (16B-aligned rows)
    __shared__ float sW[KC][64];
    __shared__ float sa[AFF ? K : 1];
    __shared__ float sd[AFF ? K : 1];

    const int tid    = threadIdx.x;
    const int rowgrp = tid >> 3;            // 0..31 -> rows rowgrp*4..+3
    const int colgrp = tid & 7;             // 0..7  -> cols colgrp*8..+7
    const int row0   = blockIdx.x * 128;

    if (AFF) {
        if (tid < K) {
            const float invN = 1.0f / (float)N_NODES;
            float m  = stats[tid] * invN;
            float vv = stats[HID + tid] * invN - m * m;
            float rs = rsqrtf(vv + BN_EPS);
            float a  = rs * gam[tid];
            sa[tid] = a;
            sd[tid] = bet[tid] - m * a;
        }
        __syncthreads();
    }

    float acc[4][8];
#pragma unroll
    for (int i = 0; i < 4; i++)
#pragma unroll
        for (int j = 0; j < 8; j++) acc[i][j] = 0.0f;

    for (int kc = 0; kc < K; kc += KC) {
        if (kc) __syncthreads();            // previous mainloop done reading

        // stage W chunk: 2048 floats, 2 float4 per thread
#pragma unroll
        for (int s = 0; s < 2; s++) {
            int slot = tid + s * 256;       // 0..511
            int k  = slot >> 4;             // 0..31
            int c4 = (slot & 15) * 4;
            *(float4*)&sW[k][c4] = *(const float4*)&W[(kc + k) * 64 + c4];
        }

        // stage X chunk transposed: 128 rows x 32 cols, 4 float4 per thread
#pragma unroll
        for (int s = 0; s < 4; s++) {
            int slot = tid + s * 256;       // 0..1023
            int r = slot >> 3;              // 0..127
            int q = (slot & 7) * 4;         // 0,4,..28
            float4 v = make_float4(0.f, 0.f, 0.f, 0.f);
            if (row0 + r < N_NODES)
                v = *(const float4*)&X[(row0 + r) * K + kc + q];
            if (AFF) {
                v.x = fmaxf(v.x * sa[kc + q]     + sd[kc + q],     0.0f);
                v.y = fmaxf(v.y * sa[kc + q + 1] + sd[kc + q + 1], 0.0f);
                v.z = fmaxf(v.z * sa[kc + q + 2] + sd[kc + q + 2], 0.0f);
                v.w = fmaxf(v.w * sa[kc + q + 3] + sd[kc + q + 3], 0.0f);
            }
            sXT[q][r]     = v.x;
            sXT[q + 1][r] = v.y;
            sXT[q + 2][r] = v.z;
            sXT[q + 3][r] = v.w;
        }
        __syncthreads();

#pragma unroll 8
        for (int k = 0; k < KC; k++) {
            float4 xv = *(const float4*)&sXT[k][rowgrp * 4];
            float4 w0 = *(const float4*)&sW[k][colgrp * 8];
            float4 w1 = *(const float4*)&sW[k][colgrp * 8 + 4];
            const float xs[4] = {xv.x, xv.y, xv.z, xv.w};
#pragma unroll
            for (int i = 0; i < 4; i++) {
                acc[i][0] += xs[i] * w0.x; acc[i][1] += xs[i] * w0.y;
                acc[i][2] += xs[i] * w0.z; acc[i][3] += xs[i] * w0.w;
                acc[i][4] += xs[i] * w1.x; acc[i][5] += xs[i] * w1.y;
                acc[i][6] += xs[i] * w1.z; acc[i][7] += xs[i] * w1.w;
            }
        }
    }

#pragma unroll
    for (int i = 0; i < 4; i++) {
        int r = row0 + rowgrp * 4 + i;
        if (r < N_NODES) {
            float* o = &T[r * 64 + colgrp * 8];
            *(float4*)o       = make_float4(acc[i][0], acc[i][1], acc[i][2], acc[i][3]);
            *(float4*)(o + 4) = make_float4(acc[i][4], acc[i][5], acc[i][6], acc[i][7]);
        }
    }
}

// ------------------------- GEMM: [N, 64] x [64, 4], BN2 affine fused ----------
__global__ void k_gemm_n4(const float* __restrict__ H, const float* __restrict__ W,
                          float* __restrict__ T, const float* __restrict__ stats,
                          const float* __restrict__ gam, const float* __restrict__ bet) {
    __shared__ float sH[64 * 65];
    __shared__ float sW[64 * 4];
    __shared__ float sa[64], sd[64];
    const int tid = threadIdx.x;
    sW[tid] = W[tid];   // 256 elems exactly
    if (tid < 64) {
        const float invN = 1.0f / (float)N_NODES;
        float m  = stats[tid] * invN;
        float vv = stats[HID + tid] * invN - m * m;
        float rs = rsqrtf(vv + BN_EPS);
        float a  = rs * gam[tid];
        sa[tid] = a;
        sd[tid] = bet[tid] - m * a;
    }
    __syncthreads();
    const int row0 = blockIdx.x * 64;
    for (int i = tid; i < 64 * 64; i += 256) {
        int r = i >> 6, k = i & 63;
        float v = 0.0f;
        if (row0 + r < N_NODES) {
            v = H[(row0 + r) * 64 + k];
            v = fmaxf(v * sa[k] + sd[k], 0.0f);
        }
        sH[r * 65 + k] = v;
    }
    __syncthreads();
    const int r = tid >> 2, c = tid & 3;
    float acc = 0.0f;
#pragma unroll 8
    for (int k = 0; k < 64; k++)
        acc += sH[r * 65 + k] * sW[k * 4 + c];
    if (row0 + r < N_NODES) T[(row0 + r) * 4 + c] = acc;
}

// ------------------------- aggregation (gather, HID=64) + fused BN stats ------
// 16 threads per node, each owning 4 contiguous columns; grid-strided groups.
__global__ void k_gather64(const float* __restrict__ T, const float* __restrict__ b,
                           float* __restrict__ A, float* __restrict__ stats) {
    const int tid = threadIdx.x;
    const int sub = tid >> 4;       // node-in-group 0..15
    const int c   = (tid & 15) * 4; // column group
    const float4 bb = *(const float4*)&b[c];

    float s0 = 0, s1 = 0, s2 = 0, s3 = 0;
    float q0 = 0, q1 = 0, q2 = 0, q3 = 0;

    for (int grp = blockIdx.x; grp < NGROUPS; grp += gridDim.x) {
        const int node = grp * 16 + sub;
        const int beg = g_off[node];
        const int end = g_off[node + 1];
        const float dv = g_dinv[node];
        const float sc = dv * dv;
        float4 t = *(const float4*)&T[node * 64 + c];
        float4 acc;
        acc.x = t.x * sc + bb.x; acc.y = t.y * sc + bb.y;
        acc.z = t.z * sc + bb.z; acc.w = t.w * sc + bb.w;

        for (int j = beg; j < end; j++) {
            int2  e  = g_edge[j];
            float cf = __int_as_float(e.y);
            float4 v = *(const float4*)&T[e.x * 64 + c];
            acc.x += v.x * cf; acc.y += v.y * cf;
            acc.z += v.z * cf; acc.w += v.w * cf;
        }
        *(float4*)&A[node * 64 + c] = acc;

        s0 += acc.x; q0 += acc.x * acc.x;
        s1 += acc.y; q1 += acc.y * acc.y;
        s2 += acc.z; q2 += acc.z * acc.z;
        s3 += acc.w; q3 += acc.w * acc.w;
    }

    __shared__ float ssum[64], ssq[64];
    if (tid < 64) { ssum[tid] = 0.0f; ssq[tid] = 0.0f; }
    __syncthreads();
    atomicAdd(&ssum[c],     s0); atomicAdd(&ssq[c],     q0);
    atomicAdd(&ssum[c + 1], s1); atomicAdd(&ssq[c + 1], q1);
    atomicAdd(&ssum[c + 2], s2); atomicAdd(&ssq[c + 2], q2);
    atomicAdd(&ssum[c + 3], s3); atomicAdd(&ssq[c + 3], q3);
    __syncthreads();
    if (tid < 64) {
        atomicAdd(&stats[tid],       ssum[tid]);
        atomicAdd(&stats[HID + tid], ssq[tid]);
    }
}

// ------------------------- aggregation (gather, N_CLS=4) ----------------------
__global__ void k_gather4(const float* __restrict__ T, const float* __restrict__ b,
                          float* __restrict__ O) {
    int node = blockIdx.x * blockDim.x + threadIdx.x;
    if (node >= N_NODES) return;
    float dv = g_dinv[node];
    float sc = dv * dv;
    float4 t = *(const float4*)&T[node * 4];
    float4 acc;
    acc.x = t.x * sc + b[0]; acc.y = t.y * sc + b[1];
    acc.z = t.z * sc + b[2]; acc.w = t.w * sc + b[3];
    int beg = g_off[node], end = g_off[node + 1];
    for (int j = beg; j < end; j++) {
        int2  e  = g_edge[j];
        float cf = __int_as_float(e.y);
        float4 v = *(const float4*)&T[e.x * 4];
        acc.x += v.x * cf; acc.y += v.y * cf;
        acc.z += v.z * cf; acc.w += v.w * cf;
    }
    *(float4*)&O[node * 4] = acc;
}

// ------------------------- launch --------------------------------------------
extern "C" void kernel_launch(void* const* d_in, const int* in_sizes, int n_in,
                              void* d_out, int out_size) {
    const float* x   = (const float*)d_in[0];
    const int*   ei  = (const int*)d_in[1];      // int32 (JAX default int)
    const float* W1  = (const float*)d_in[2];
    const float* b1  = (const float*)d_in[3];
    const float* g1  = (const float*)d_in[4];
    const float* be1 = (const float*)d_in[5];
    const float* W2  = (const float*)d_in[6];
    const float* b2  = (const float*)d_in[7];
    const float* g2  = (const float*)d_in[8];
    const float* be2 = (const float*)d_in[9];
    const float* W3  = (const float*)d_in[10];
    const float* b3  = (const float*)d_in[11];
    float* out = (float*)d_out;

    float *bufA, *bufB, *st1, *st2;
    cudaGetSymbolAddress((void**)&bufA, g_bufA);
    cudaGetSymbolAddress((void**)&bufB, g_bufB);
    cudaGetSymbolAddress((void**)&st1,  g_stats1);
    cudaGetSymbolAddress((void**)&st2,  g_stats2);

    const int TB = 256;
    const int gN    = (N_NODES + TB - 1) / TB;          // 391
    const int gE    = (N_EDGES + TB - 1) / TB;          // 6250
    const int gM128 = (N_NODES + 127) / 128;            // 782
    const int gM64  = (N_NODES + 63) / 64;              // 1563

    // graph prep: degrees (+stat zero), scan (+dinv), CSR build
    k_zero_cnt<<<gN, TB>>>();
    k_count<<<gE, TB>>>(ei);
    k_scan1<<<SCAN_NB, SCAN_BS>>>();
    k_scan2<<<1, 256>>>();
    k_scan3<<<gN, TB>>>();
    k_fill<<<gE, TB>>>(ei);

    // layer 1: t1 = x @ W1 ; h1 = aggregate(t1) (+BN1 stats)
    k_gemm_n64<IN_F, false><<<gM128, TB>>>(x, W1, bufA, nullptr, nullptr, nullptr);
    k_gather64<<<GATHER_GRID, TB>>>(bufA, b1, bufB, st1);

    // layer 2: t2 = relu(bn1(h1)) @ W2 ; h2 = aggregate(t2) (+BN2 stats)
    k_gemm_n64<HID, true><<<gM128, TB>>>(bufB, W2, bufA, st1, g1, be1);
    k_gather64<<<GATHER_GRID, TB>>>(bufA, b2, bufB, st2);

    // layer 3: t3 = relu(bn2(h2)) @ W3 ; out = aggregate(t3)
    k_gemm_n4<<<gM64, TB>>>(bufB, W3, bufA, st2, g2, be2);
    k_gather4<<<gN, TB>>>(bufA, b3, out);
}